// round 6
// baseline (speedup 1.0000x reference)
#include <cuda_runtime.h>
#include <cuda_bf16.h>
#include <math.h>
#include <stdint.h>

#define BATCH   8
#define S_LEN   1024
#define DM      1024
#define HEADS   16
#define DK      64
#define M_ROWS  (BATCH * S_LEN)   // 8192

typedef __nv_bfloat16 bf16;

// ------------------------- device scratch (no allocs allowed) ---------------
__device__ bf16 g_Qhi[M_ROWS * DM];
__device__ bf16 g_Qlo[M_ROWS * DM];
__device__ bf16 g_Khi[M_ROWS * DM];
__device__ bf16 g_Klo[M_ROWS * DM];
__device__ bf16 g_Vhi[M_ROWS * DM];
__device__ bf16 g_Vlo[M_ROWS * DM];
__device__ bf16 g_Ohi[M_ROWS * DM];
__device__ bf16 g_Olo[M_ROWS * DM];
__device__ bf16 g_A3hi[3 * M_ROWS * DM];
__device__ bf16 g_A3lo[3 * M_ROWS * DM];
__device__ bf16 g_Whi[4 * DM * DM];
__device__ bf16 g_Wlo[4 * DM * DM];

// ------------------------- helpers -----------------------------------------
__device__ __forceinline__ uint32_t smem_u32(const void* p) {
    return (uint32_t)__cvta_generic_to_shared(p);
}
__device__ __forceinline__ void cpa16(uint32_t smem_addr, const void* g) {
    asm volatile("cp.async.cg.shared.global [%0], [%1], 16;" :: "r"(smem_addr), "l"(g));
}
__device__ __forceinline__ float ex2(float x) {
    float r;
    asm("ex2.approx.f32 %0, %1;" : "=f"(r) : "f"(x));
    return r;
}
__device__ __forceinline__ uint32_t packbf(float lo, float hi) {
    uint32_t r;
    asm("cvt.rn.bf16x2.f32 %0, %1, %2;" : "=r"(r) : "f"(hi), "f"(lo));
    return r;
}

#define LDSM4(r, addr) \
    asm volatile("ldmatrix.sync.aligned.m8n8.x4.shared.b16 {%0,%1,%2,%3}, [%4];" \
        : "=r"((r)[0]), "=r"((r)[1]), "=r"((r)[2]), "=r"((r)[3]) : "r"(addr))

#define LDSM4T(r, addr) \
    asm volatile("ldmatrix.sync.aligned.m8n8.x4.trans.shared.b16 {%0,%1,%2,%3}, [%4];" \
        : "=r"((r)[0]), "=r"((r)[1]), "=r"((r)[2]), "=r"((r)[3]) : "r"(addr))

#define MMA16816(d, a, b0, b1) \
    asm volatile("mma.sync.aligned.m16n8k16.row.col.f32.bf16.bf16.f32 " \
        "{%0,%1,%2,%3}, {%4,%5,%6,%7}, {%8,%9}, {%0,%1,%2,%3};" \
        : "+f"((d)[0]), "+f"((d)[1]), "+f"((d)[2]), "+f"((d)[3]) \
        : "r"((a)[0]), "r"((a)[1]), "r"((a)[2]), "r"((a)[3]), "r"(b0), "r"(b1))

// ------------------------- GEMM (projections) -------------------------------
#define KSTEP     16
#define NKI       (DM / KSTEP)        // 64
#define ROW_B     48
#define REGION_B  (128 * ROW_B)       // 6144
#define STAGE_B   (4 * REGION_B)      // 24576
#define GEMM_SMEM (4 * STAGE_B)       // 98304 (4-stage ring)

__device__ __forceinline__ void load_stage(
    uint32_t stg,
    const bf16* __restrict__ Ahi, const bf16* __restrict__ Alo,
    const bf16* __restrict__ Bhi, const bf16* __restrict__ Blo,
    int aRow0, int bRow0, int k0, int tid)
{
    const int row = tid >> 1;
    const int ch  = tid & 1;
    const uint32_t soff = (uint32_t)(row * ROW_B + ch * 16);
    const size_t ga = (size_t)(aRow0 + row) * DM + k0 + ch * 8;
    const size_t gb = (size_t)(bRow0 + row) * DM + k0 + ch * 8;
    cpa16(stg + 0 * REGION_B + soff, Ahi + ga);
    cpa16(stg + 1 * REGION_B + soff, Alo + ga);
    cpa16(stg + 2 * REGION_B + soff, Bhi + gb);
    cpa16(stg + 3 * REGION_B + soff, Blo + gb);
}

// MODE 0: f32 C + bias.   MODE 1: bf16 hi/lo split outputs (bias added first).
template<int MODE>
__global__ __launch_bounds__(256, 2)
void gemm3(const bf16* __restrict__ A0hi, const bf16* __restrict__ A0lo,
           const bf16* __restrict__ A1hi, const bf16* __restrict__ A1lo,
           const bf16* __restrict__ A2hi, const bf16* __restrict__ A2lo,
           const bf16* __restrict__ Wh,   const bf16* __restrict__ Wl,
           const float* __restrict__ bias0, const float* __restrict__ bias1,
           const float* __restrict__ bias2,
           float* __restrict__ C,
           bf16* __restrict__ C0hi, bf16* __restrict__ C0lo,
           bf16* __restrict__ C1hi, bf16* __restrict__ C1lo,
           bf16* __restrict__ C2hi, bf16* __restrict__ C2lo)
{
    extern __shared__ char smc[];
    const uint32_t sbase = smem_u32(smc);
    const int z = blockIdx.z;
    const bf16* Ahi = (z == 0) ? A0hi : (z == 1) ? A1hi : A2hi;
    const bf16* Alo = (z == 0) ? A0lo : (z == 1) ? A1lo : A2lo;
    const bf16* Bhi = Wh + (size_t)z * DM * DM;
    const bf16* Blo = Wl + (size_t)z * DM * DM;
    const float* bias = (z == 0) ? bias0 : (z == 1) ? bias1 : bias2;
    bf16* Chi = (z == 0) ? C0hi : (z == 1) ? C1hi : C2hi;
    bf16* Clo = (z == 0) ? C0lo : (z == 1) ? C1lo : C2lo;

    const int tid  = threadIdx.x;
    const int wid  = tid >> 5;
    const int lane = tid & 31;
    const int M0 = (wid & 3) * 32;
    const int N0 = (wid >> 2) * 64;
    const int aRow0 = blockIdx.y * 128;
    const int bRow0 = blockIdx.x * 128;

    const int la_row = (lane & 7) + ((lane >> 3) & 1) * 8;
    const int la_k   = (lane >> 4) * 8;
    const uint32_t aoff = (uint32_t)((M0 + la_row) * ROW_B + la_k * 2);
    const int lb_row = ((lane >> 4) * 8) + (lane & 7);
    const int lb_k   = ((lane >> 3) & 1) * 8;
    const uint32_t boff = (uint32_t)((N0 + lb_row) * ROW_B + lb_k * 2);

    float acc[2][8][4];
    #pragma unroll
    for (int i = 0; i < 2; i++)
        #pragma unroll
        for (int j = 0; j < 8; j++)
            #pragma unroll
            for (int v = 0; v < 4; v++) acc[i][j][v] = 0.f;

    // prologue: fill 3 of 4 ring slots
    load_stage(sbase + 0 * STAGE_B, Ahi, Alo, Bhi, Blo, aRow0, bRow0, 0 * KSTEP, tid);
    asm volatile("cp.async.commit_group;" ::: "memory");
    load_stage(sbase + 1 * STAGE_B, Ahi, Alo, Bhi, Blo, aRow0, bRow0, 1 * KSTEP, tid);
    asm volatile("cp.async.commit_group;" ::: "memory");
    load_stage(sbase + 2 * STAGE_B, Ahi, Alo, Bhi, Blo, aRow0, bRow0, 2 * KSTEP, tid);
    asm volatile("cp.async.commit_group;" ::: "memory");

    for (int kt = 0; kt < NKI; kt++) {
        const uint32_t stg = sbase + (uint32_t)(kt & 3) * STAGE_B;

        if (kt < NKI - 2)       asm volatile("cp.async.wait_group 2;" ::: "memory");
        else if (kt == NKI - 2) asm volatile("cp.async.wait_group 1;" ::: "memory");
        else                    asm volatile("cp.async.wait_group 0;" ::: "memory");
        __syncthreads();   // single barrier; prefetch below targets slot freed last iter

        uint32_t ah[2][4], al[2][4];
        LDSM4(ah[0], stg + 0 * REGION_B + aoff);
        LDSM4(ah[1], stg + 0 * REGION_B + aoff + 16 * ROW_B);
        LDSM4(al[0], stg + 1 * REGION_B + aoff);
        LDSM4(al[1], stg + 1 * REGION_B + aoff + 16 * ROW_B);

        #pragma unroll
        for (int np = 0; np < 4; np++) {
            const int npx = (np + wid) & 3;   // per-warp skew spreads LDS bursts
            uint32_t bh[4], bl[4];
            LDSM4(bh, stg + 2 * REGION_B + boff + npx * 16 * ROW_B);
            LDSM4(bl, stg + 3 * REGION_B + boff + npx * 16 * ROW_B);
            #pragma unroll
            for (int mf = 0; mf < 2; mf++) {
                float* d0 = acc[mf][npx * 2 + 0];
                float* d1 = acc[mf][npx * 2 + 1];
                MMA16816(d0, ah[mf], bh[0], bh[1]);
                MMA16816(d1, ah[mf], bh[2], bh[3]);
                MMA16816(d0, ah[mf], bl[0], bl[1]);
                MMA16816(d1, ah[mf], bl[2], bl[3]);
                MMA16816(d0, al[mf], bh[0], bh[1]);
                MMA16816(d1, al[mf], bh[2], bh[3]);
            }
        }

        if (kt + 3 < NKI) {
            load_stage(sbase + (uint32_t)((kt + 3) & 3) * STAGE_B, Ahi, Alo, Bhi, Blo,
                       aRow0, bRow0, (kt + 3) * KSTEP, tid);
            asm volatile("cp.async.commit_group;" ::: "memory");
        }
    }

    #pragma unroll
    for (int mf = 0; mf < 2; mf++) {
        const int row = aRow0 + M0 + mf * 16 + (lane >> 2);
        #pragma unroll
        for (int nf = 0; nf < 8; nf++) {
            const int col = bRow0 + N0 + nf * 8 + (lane & 3) * 2;
            const float b0 = bias[col], b1 = bias[col + 1];
            float f0 = acc[mf][nf][0] + b0, f1 = acc[mf][nf][1] + b1;
            float f2 = acc[mf][nf][2] + b0, f3 = acc[mf][nf][3] + b1;
            if (MODE == 0) {
                *(float2*)(C + (size_t)row * DM + col)       = make_float2(f0, f1);
                *(float2*)(C + (size_t)(row + 8) * DM + col) = make_float2(f2, f3);
            } else {
                uint32_t uh0 = packbf(f0, f1);
                float e0 = __uint_as_float(uh0 << 16);
                float e1 = __uint_as_float(uh0 & 0xffff0000u);
                uint32_t ul0 = packbf(f0 - e0, f1 - e1);
                uint32_t uh1 = packbf(f2, f3);
                float e2 = __uint_as_float(uh1 << 16);
                float e3 = __uint_as_float(uh1 & 0xffff0000u);
                uint32_t ul1 = packbf(f2 - e2, f3 - e3);
                *(uint32_t*)(Chi + (size_t)row * DM + col)       = uh0;
                *(uint32_t*)(Clo + (size_t)row * DM + col)       = ul0;
                *(uint32_t*)(Chi + (size_t)(row + 8) * DM + col) = uh1;
                *(uint32_t*)(Clo + (size_t)(row + 8) * DM + col) = ul1;
            }
        }
    }
}

// ------------------------- hi/lo split (3 inputs batched) -------------------
__global__ __launch_bounds__(256)
void split_act3(const float4* __restrict__ in0, const float4* __restrict__ in1,
                const float4* __restrict__ in2, bf16* __restrict__ hi,
                bf16* __restrict__ lo, int n4)
{
    int i = blockIdx.x * 256 + threadIdx.x;
    if (i >= n4) return;
    const int y = blockIdx.y;
    const float4* in = (y == 0) ? in0 : (y == 1) ? in1 : in2;
    const size_t o = (size_t)y * (size_t)n4 * 4 + (size_t)i * 4;
    float4 v = in[i];
    uint32_t h0 = packbf(v.x, v.y);
    uint32_t h1 = packbf(v.z, v.w);
    float e0 = __uint_as_float(h0 << 16), e1 = __uint_as_float(h0 & 0xffff0000u);
    float e2 = __uint_as_float(h1 << 16), e3 = __uint_as_float(h1 & 0xffff0000u);
    uint32_t l0 = packbf(v.x - e0, v.y - e1);
    uint32_t l1 = packbf(v.z - e2, v.w - e3);
    *(uint2*)(hi + o) = make_uint2(h0, h1);
    *(uint2*)(lo + o) = make_uint2(l0, l1);
}

// ------------------------- weight transpose + split (4 batched) -------------
__global__ __launch_bounds__(256)
void transpose_split_w4(const float* __restrict__ W0, const float* __restrict__ W1,
                        const float* __restrict__ W2, const float* __restrict__ W3,
                        bf16* __restrict__ hi, bf16* __restrict__ lo)
{
    __shared__ float t[32][33];
    const int z = blockIdx.z;
    const float* W = (z == 0) ? W0 : (z == 1) ? W1 : (z == 2) ? W2 : W3;
    const size_t zofs = (size_t)z * DM * DM;
    const int n0 = blockIdx.x * 32;
    const int k0 = blockIdx.y * 32;
    const int tx = threadIdx.x & 31;
    const int ty = threadIdx.x >> 5;
    #pragma unroll
    for (int r = ty; r < 32; r += 8)
        t[r][tx] = W[(size_t)(k0 + r) * DM + n0 + tx];
    __syncthreads();
    #pragma unroll
    for (int r = ty; r < 32; r += 8) {
        float x = t[tx][r];
        bf16 h = __float2bfloat16_rn(x);
        size_t o = zofs + (size_t)(n0 + r) * DM + k0 + tx;
        hi[o] = h;
        lo[o] = __float2bfloat16_rn(x - __bfloat162float(h));
    }
}

// ------------------------- flash attention (tensor-core bf16x3) -------------
// Br=128 q rows per CTA (8 warps x 16 rows), Bc=64, 3-stage KV ring.
#define FROW   144
#define FREG   (64 * FROW)            // 9216  (one 64-row region)
#define QREG   (128 * FROW)           // 18432 (one 128-row Q region)
#define FSTAGE (4 * FREG + 256)       // 37120 (Khi,Klo,Vhi,Vlo + mask)
#define FLASH_SMEM (3 * FSTAGE)       // 111360
#define NT     (S_LEN / 64)           // 16

__device__ __forceinline__ void load_kv_stage(
    uint32_t stg,
    const bf16* __restrict__ Khi, const bf16* __restrict__ Klo,
    const bf16* __restrict__ Vhi, const bf16* __restrict__ Vlo,
    const int* __restrict__ mask, int b, int hcol, int k0, int tid)
{
    #pragma unroll
    for (int i = 0; i < 2; i++) {
        const int c = tid + 256 * i;
        const int r = c >> 3;
        const int cc = c & 7;
        const uint32_t so = (uint32_t)(r * FROW + cc * 16);
        const size_t g = (size_t)(b * S_LEN + k0 + r) * DM + hcol + cc * 8;
        cpa16(stg + 0 * FREG + so, Khi + g);
        cpa16(stg + 1 * FREG + so, Klo + g);
        cpa16(stg + 2 * FREG + so, Vhi + g);
        cpa16(stg + 3 * FREG + so, Vlo + g);
    }
    if (tid < 16)
        cpa16(stg + 4 * FREG + tid * 16, mask + b * S_LEN + k0 + tid * 4);
}

__global__ __launch_bounds__(256, 1)
void flash_attn_tc(const bf16* __restrict__ Qhi, const bf16* __restrict__ Qlo,
                   const bf16* __restrict__ Khi, const bf16* __restrict__ Klo,
                   const bf16* __restrict__ Vhi, const bf16* __restrict__ Vlo,
                   const int* __restrict__ mask,
                   bf16* __restrict__ Ohi, bf16* __restrict__ Olo)
{
    extern __shared__ char smf[];
    const uint32_t base = smem_u32(smf);
    const int tid  = threadIdx.x;
    const int wid  = tid >> 5;
    const int lane = tid & 31;
    const int b  = blockIdx.z;
    const int h  = blockIdx.y;
    const int q0 = blockIdx.x * 128;
    const int hcol = h * DK;

    // ---- stage Q (128 rows, hi+lo) through slot0, then to registers ----
    #pragma unroll
    for (int i = 0; i < 4; i++) {
        const int c = tid + 256 * i;
        const int r = c >> 3;
        const int cc = c & 7;
        const uint32_t so = (uint32_t)(r * FROW + cc * 16);
        const size_t g = (size_t)(b * S_LEN + q0 + r) * DM + hcol + cc * 8;
        cpa16(base + so,        Qhi + g);
        cpa16(base + QREG + so, Qlo + g);
    }
    asm volatile("cp.async.commit_group;" ::: "memory");
    asm volatile("cp.async.wait_group 0;" ::: "memory");
    __syncthreads();

    const int la_row = (lane & 7) + ((lane >> 3) & 1) * 8;
    const int la_k   = (lane >> 4) * 8;
    uint32_t qh[4][4], ql[4][4];
    {
        const uint32_t qaddr = base + (uint32_t)((wid * 16 + la_row) * FROW + la_k * 2);
        #pragma unroll
        for (int kf = 0; kf < 4; kf++) {
            LDSM4(qh[kf], qaddr + kf * 32);
            LDSM4(ql[kf], qaddr + QREG + kf * 32);
        }
    }
    __syncthreads();   // Q reads done before KV ring overwrites slot0

    // ---- prologue: fill 2 of 3 ring slots ----
    load_kv_stage(base + 0 * FSTAGE, Khi, Klo, Vhi, Vlo, mask, b, hcol, 0,  tid);
    asm volatile("cp.async.commit_group;" ::: "memory");
    load_kv_stage(base + 1 * FSTAGE, Khi, Klo, Vhi, Vlo, mask, b, hcol, 64, tid);
    asm volatile("cp.async.commit_group;" ::: "memory");

    const int lb_row = ((lane >> 4) * 8) + (lane & 7);
    const int lb_k   = ((lane >> 3) & 1) * 8;
    const int vb_row = (lane & 7) + ((lane >> 3) & 1) * 8;
    const int vb_col = (lane >> 4) * 8;

    float m2[2] = {-INFINITY, -INFINITY};
    float l2[2] = {0.f, 0.f};
    float oacc[4][8];
    #pragma unroll
    for (int i = 0; i < 4; i++)
        #pragma unroll
        for (int j = 0; j < 8; j++) oacc[i][j] = 0.f;

    const float C1   = 0.04508422f;          // log2(e)/32
    const float MNEG = -1e20f * 0.04508422f;

    for (int t = 0; t < NT; t++) {
        int slot = t % 3;
        const uint32_t stg = base + (uint32_t)slot * FSTAGE;

        if (t == NT - 1) asm volatile("cp.async.wait_group 0;" ::: "memory");
        else             asm volatile("cp.async.wait_group 1;" ::: "memory");
        __syncthreads();   // single barrier; prefetch below hits slot freed last iter

        // ---- S = Q K^T (3-term), per-warp np skew ----
        float sacc[4][8];
        #pragma unroll
        for (int np = 0; np < 4; np++)
            #pragma unroll
            for (int j = 0; j < 8; j++) sacc[np][j] = 0.f;

        #pragma unroll
        for (int np = 0; np < 4; np++) {
            const int npx = (np + wid) & 3;
            const uint32_t kb = stg + (uint32_t)((npx * 16 + lb_row) * FROW + lb_k * 2);
            float* d0 = &sacc[npx][0];
            float* d1 = &sacc[npx][4];
            #pragma unroll
            for (int kf = 0; kf < 4; kf++) {
                uint32_t kh[4], kl[4];
                LDSM4(kh, kb + kf * 32);
                LDSM4(kl, kb + FREG + kf * 32);
                MMA16816(d0, qh[kf], kh[0], kh[1]);
                MMA16816(d1, qh[kf], kh[2], kh[3]);
                MMA16816(d0, qh[kf], kl[0], kl[1]);
                MMA16816(d1, qh[kf], kl[2], kl[3]);
                MMA16816(d0, ql[kf], kh[0], kh[1]);
                MMA16816(d1, ql[kf], kh[2], kh[3]);
            }
        }

        // ---- mask + scale ----
        const char* mbase = smf + slot * FSTAGE + 4 * FREG;
        #pragma unroll
        for (int np = 0; np < 4; np++) {
            #pragma unroll
            for (int h2 = 0; h2 < 2; h2++) {
                const int col = np * 16 + h2 * 8 + 2 * (lane & 3);
                int2 mv = *(const int2*)(mbase + col * 4);
                float* d = &sacc[np][h2 * 4];
                d[0] = mv.x ? d[0] * C1 : MNEG;
                d[1] = mv.y ? d[1] * C1 : MNEG;
                d[2] = mv.x ? d[2] * C1 : MNEG;
                d[3] = mv.y ? d[3] * C1 : MNEG;
            }
        }

        // ---- online softmax ----
        float mx0 = -INFINITY, mx1 = -INFINITY;
        #pragma unroll
        for (int np = 0; np < 4; np++)
            #pragma unroll
            for (int h2 = 0; h2 < 2; h2++) {
                float* d = &sacc[np][h2 * 4];
                mx0 = fmaxf(mx0, fmaxf(d[0], d[1]));
                mx1 = fmaxf(mx1, fmaxf(d[2], d[3]));
            }
        mx0 = fmaxf(mx0, __shfl_xor_sync(0xffffffffu, mx0, 1));
        mx0 = fmaxf(mx0, __shfl_xor_sync(0xffffffffu, mx0, 2));
        mx1 = fmaxf(mx1, __shfl_xor_sync(0xffffffffu, mx1, 1));
        mx1 = fmaxf(mx1, __shfl_xor_sync(0xffffffffu, mx1, 2));

        const float mn0 = fmaxf(m2[0], mx0);
        const float mn1 = fmaxf(m2[1], mx1);
        const float a0 = ex2(m2[0] - mn0);
        const float a1 = ex2(m2[1] - mn1);
        m2[0] = mn0; m2[1] = mn1;

        float ls0 = 0.f, ls1 = 0.f;
        #pragma unroll
        for (int np = 0; np < 4; np++)
            #pragma unroll
            for (int h2 = 0; h2 < 2; h2++) {
                float* d = &sacc[np][h2 * 4];
                d[0] = ex2(d[0] - mn0);
                d[1] = ex2(d[1] - mn0);
                d[2] = ex2(d[2] - mn1);
                d[3] = ex2(d[3] - mn1);
                ls0 += d[0] + d[1];
                ls1 += d[2] + d[3];
            }
        ls0 += __shfl_xor_sync(0xffffffffu, ls0, 1);
        ls0 += __shfl_xor_sync(0xffffffffu, ls0, 2);
        ls1 += __shfl_xor_sync(0xffffffffu, ls1, 1);
        ls1 += __shfl_xor_sync(0xffffffffu, ls1, 2);
        l2[0] = l2[0] * a0 + ls0;
        l2[1] = l2[1] * a1 + ls1;

        #pragma unroll
        for (int np = 0; np < 4; np++)
            #pragma unroll
            for (int h2 = 0; h2 < 2; h2++) {
                float* d = &oacc[np][h2 * 4];
                d[0] *= a0; d[1] *= a0; d[2] *= a1; d[3] *= a1;
            }

        // ---- P -> bf16 hi/lo A-fragments ----
        uint32_t phi[4][4], plo[4][4];
        #pragma unroll
        for (int np = 0; np < 4; np++) {
            #pragma unroll
            for (int h2 = 0; h2 < 2; h2++) {
                float* d = &sacc[np][h2 * 4];
                uint32_t u01 = packbf(d[0], d[1]);
                uint32_t u23 = packbf(d[2], d[3]);
                float e0 = __uint_as_float(u01 << 16), e1 = __uint_as_float(u01 & 0xffff0000u);
                float e2 = __uint_as_float(u23 << 16), e3 = __uint_as_float(u23 & 0xffff0000u);
                phi[np][h2 * 2 + 0] = u01;
                phi[np][h2 * 2 + 1] = u23;
                plo[np][h2 * 2 + 0] = packbf(d[0] - e0, d[1] - e1);
                plo[np][h2 * 2 + 1] = packbf(d[2] - e2, d[3] - e3);
            }
        }

        // ---- O += P V (3-term), per-warp npd skew ----
        #pragma unroll
        for (int npd = 0; npd < 4; npd++) {
            const int npdx = (npd + wid) & 3;
            float* o0 = &oacc[npdx][0];
            float* o1 = &oacc[npdx][4];
            #pragma unroll
            for (int kf = 0; kf < 4; kf++) {
                const uint32_t va = stg + 2 * FREG +
                    (uint32_t)((kf * 16 + vb_row) * FROW + (npdx * 16 + vb_col) * 2);
                uint32_t vh[4], vl[4];
                LDSM4T(vh, va);
                LDSM4T(vl, va + FREG);
                MMA16816(o0, phi[kf], vh[0], vh[1]);
                MMA16816(o1, phi[kf], vh[2], vh[3]);
                MMA16816(o0, phi[kf], vl[0], vl[1]);
                MMA16816(o1, phi[kf], vl[2], vl[3]);
                MMA16816(o0, plo[kf], vh[0], vh[1]);
                MMA16816(o1, plo[kf], vh[2], vh[3]);
            }
        }

        if (t + 2 < NT) {
            load_kv_stage(base + (uint32_t)((t + 2) % 3) * FSTAGE,
                          Khi, Klo, Vhi, Vlo, mask, b, hcol, (t + 2) * 64, tid);
            asm volatile("cp.async.commit_group;" ::: "memory");
        }
    }

    // ---- finalize: O/l -> bf16 hi/lo ----
    const float inv0 = 1.f / l2[0];
    const float inv1 = 1.f / l2[1];
    const int r0 = q0 + wid * 16 + (lane >> 2);
    const size_t row0 = (size_t)(b * S_LEN + r0) * DM + hcol;
    const size_t row1 = row0 + 8 * DM;
    #pragma unroll
    for (int npd = 0; npd < 4; npd++) {
        #pragma unroll
        for (int h2 = 0; h2 < 2; h2++) {
            const int c = npd * 16 + h2 * 8 + 2 * (lane & 3);
            float* d = &oacc[npd][h2 * 4];
            float f0 = d[0] * inv0, f1 = d[1] * inv0;
            float f2 = d[2] * inv1, f3 = d[3] * inv1;
            uint32_t uh0 = packbf(f0, f1);
            float e0 = __uint_as_float(uh0 << 16), e1 = __uint_as_float(uh0 & 0xffff0000u);
            uint32_t ul0 = packbf(f0 - e0, f1 - e1);
            uint32_t uh1 = packbf(f2, f3);
            float e2 = __uint_as_float(uh1 << 16), e3 = __uint_as_float(uh1 & 0xffff0000u);
            uint32_t ul1 = packbf(f2 - e2, f3 - e3);
            *(uint32_t*)(Ohi + row0 + c) = uh0;
            *(uint32_t*)(Olo + row0 + c) = ul0;
            *(uint32_t*)(Ohi + row1 + c) = uh1;
            *(uint32_t*)(Olo + row1 + c) = ul1;
        }
    }
}

// ---------------------------------------------------------------------------
extern "C" void kernel_launch(void* const* d_in, const int* in_sizes, int n_in,
                              void* d_out, int out_size)
{
    const float* values = (const float*)d_in[0];
    const float* keys   = (const float*)d_in[1];
    const float* query  = (const float*)d_in[2];
    const int*   mask   = (const int*)  d_in[3];
    const float* Wq = (const float*)d_in[4];
    const float* bq = (const float*)d_in[5];
    const float* Wk = (const float*)d_in[6];
    const float* bk = (const float*)d_in[7];
    const float* Wv = (const float*)d_in[8];
    const float* bv = (const float*)d_in[9];
    const float* Wo = (const float*)d_in[10];
    const float* bo = (const float*)d_in[11];
    float* out = (float*)d_out;

    bf16 *Qhi, *Qlo, *Khi, *Klo, *Vhi, *Vlo, *Ohi, *Olo, *A3hi, *A3lo, *Whi, *Wlo;
    cudaGetSymbolAddress((void**)&Qhi, g_Qhi);
    cudaGetSymbolAddress((void**)&Qlo, g_Qlo);
    cudaGetSymbolAddress((void**)&Khi, g_Khi);
    cudaGetSymbolAddress((void**)&Klo, g_Klo);
    cudaGetSymbolAddress((void**)&Vhi, g_Vhi);
    cudaGetSymbolAddress((void**)&Vlo, g_Vlo);
    cudaGetSymbolAddress((void**)&Ohi, g_Ohi);
    cudaGetSymbolAddress((void**)&Olo, g_Olo);
    cudaGetSymbolAddress((void**)&A3hi, g_A3hi);
    cudaGetSymbolAddress((void**)&A3lo, g_A3lo);
    cudaGetSymbolAddress((void**)&Whi, g_Whi);
    cudaGetSymbolAddress((void**)&Wlo, g_Wlo);

    cudaFuncSetAttribute(gemm3<0>, cudaFuncAttributeMaxDynamicSharedMemorySize, GEMM_SMEM);
    cudaFuncSetAttribute(gemm3<1>, cudaFuncAttributeMaxDynamicSharedMemorySize, GEMM_SMEM);
    cudaFuncSetAttribute(flash_attn_tc, cudaFuncAttributeMaxDynamicSharedMemorySize, FLASH_SMEM);

    const size_t SZ = (size_t)M_ROWS * DM;
    const int n4 = (int)(SZ / 4);

    transpose_split_w4<<<dim3(DM / 32, DM / 32, 4), 256>>>(Wq, Wk, Wv, Wo, Whi, Wlo);

    split_act3<<<dim3(n4 / 256, 3), 256>>>((const float4*)query, (const float4*)keys,
                                           (const float4*)values, A3hi, A3lo, n4);

    gemm3<1><<<dim3(DM / 128, M_ROWS / 128, 3), 256, GEMM_SMEM>>>(
        A3hi, A3lo, A3hi + SZ, A3lo + SZ, A3hi + 2 * SZ, A3lo + 2 * SZ,
        Whi, Wlo, bq, bk, bv,
        nullptr, Qhi, Qlo, Khi, Klo, Vhi, Vlo);

    dim3 gattn(S_LEN / 128, HEADS, BATCH);   // (8, 16, 8) = 1024 CTAs
    flash_attn_tc<<<gattn, 256, FLASH_SMEM>>>(Qhi, Qlo, Khi, Klo, Vhi, Vlo, mask, Ohi, Olo);

    gemm3<0><<<dim3(DM / 128, M_ROWS / 128, 1), 256, GEMM_SMEM>>>(
        Ohi, Olo, nullptr, nullptr, nullptr, nullptr,
        Whi + 3 * (size_t)DM * DM, Wlo + 3 * (size_t)DM * DM, bo, nullptr, nullptr,
        out, nullptr, nullptr, nullptr, nullptr, nullptr, nullptr);
}

// round 7
// speedup vs baseline: 2.5148x; 2.5148x over previous
#include <cuda_runtime.h>
#include <cuda_bf16.h>
#include <math.h>
#include <stdint.h>

#define BATCH   8
#define S_LEN   1024
#define DM      1024
#define HEADS   16
#define DK      64
#define M_ROWS  (BATCH * S_LEN)   // 8192

typedef __nv_bfloat16 bf16;

// ------------------------- device scratch (no allocs allowed) ---------------
__device__ bf16 g_Qhi[M_ROWS * DM];
__device__ bf16 g_Qlo[M_ROWS * DM];
__device__ bf16 g_Khi[M_ROWS * DM];
__device__ bf16 g_Klo[M_ROWS * DM];
__device__ bf16 g_Vhi[M_ROWS * DM];
__device__ bf16 g_Vlo[M_ROWS * DM];
__device__ bf16 g_Ohi[M_ROWS * DM];
__device__ bf16 g_Olo[M_ROWS * DM];
__device__ bf16 g_A3hi[3 * M_ROWS * DM];
__device__ bf16 g_A3lo[3 * M_ROWS * DM];
__device__ bf16 g_Whi[4 * DM * DM];
__device__ bf16 g_Wlo[4 * DM * DM];

// ------------------------- helpers -----------------------------------------
__device__ __forceinline__ uint32_t smem_u32(const void* p) {
    return (uint32_t)__cvta_generic_to_shared(p);
}
__device__ __forceinline__ void cpa16(uint32_t smem_addr, const void* g) {
    asm volatile("cp.async.cg.shared.global [%0], [%1], 16;" :: "r"(smem_addr), "l"(g));
}
__device__ __forceinline__ float ex2(float x) {
    float r;
    asm("ex2.approx.f32 %0, %1;" : "=f"(r) : "f"(x));
    return r;
}
__device__ __forceinline__ uint32_t packbf(float lo, float hi) {
    uint32_t r;
    asm("cvt.rn.bf16x2.f32 %0, %1, %2;" : "=r"(r) : "f"(hi), "f"(lo));
    return r;
}

#define LDSM4(r, addr) \
    asm volatile("ldmatrix.sync.aligned.m8n8.x4.shared.b16 {%0,%1,%2,%3}, [%4];" \
        : "=r"((r)[0]), "=r"((r)[1]), "=r"((r)[2]), "=r"((r)[3]) : "r"(addr))

#define LDSM4T(r, addr) \
    asm volatile("ldmatrix.sync.aligned.m8n8.x4.trans.shared.b16 {%0,%1,%2,%3}, [%4];" \
        : "=r"((r)[0]), "=r"((r)[1]), "=r"((r)[2]), "=r"((r)[3]) : "r"(addr))

#define MMA16816(d, a, b0, b1) \
    asm volatile("mma.sync.aligned.m16n8k16.row.col.f32.bf16.bf16.f32 " \
        "{%0,%1,%2,%3}, {%4,%5,%6,%7}, {%8,%9}, {%0,%1,%2,%3};" \
        : "+f"((d)[0]), "+f"((d)[1]), "+f"((d)[2]), "+f"((d)[3]) \
        : "r"((a)[0]), "r"((a)[1]), "r"((a)[2]), "r"((a)[3]), "r"(b0), "r"(b1))

// ------------------------- GEMM (projections) -------------------------------
#define KSTEP     16
#define NKI       (DM / KSTEP)        // 64
#define ROW_B     48
#define REGION_B  (128 * ROW_B)       // 6144
#define STAGE_B   (4 * REGION_B)      // 24576
#define GEMM_SMEM (4 * STAGE_B)       // 98304 (4-stage ring)

__device__ __forceinline__ void load_stage(
    uint32_t stg,
    const bf16* __restrict__ Ahi, const bf16* __restrict__ Alo,
    const bf16* __restrict__ Bhi, const bf16* __restrict__ Blo,
    int aRow0, int bRow0, int k0, int tid)
{
    const int row = tid >> 1;
    const int ch  = tid & 1;
    const uint32_t soff = (uint32_t)(row * ROW_B + ch * 16);
    const size_t ga = (size_t)(aRow0 + row) * DM + k0 + ch * 8;
    const size_t gb = (size_t)(bRow0 + row) * DM + k0 + ch * 8;
    cpa16(stg + 0 * REGION_B + soff, Ahi + ga);
    cpa16(stg + 1 * REGION_B + soff, Alo + ga);
    cpa16(stg + 2 * REGION_B + soff, Bhi + gb);
    cpa16(stg + 3 * REGION_B + soff, Blo + gb);
}

// MODE 0: f32 C + bias.   MODE 1: bf16 hi/lo split outputs (bias added first).
template<int MODE>
__global__ __launch_bounds__(256, 2)
void gemm3(const bf16* __restrict__ A0hi, const bf16* __restrict__ A0lo,
           const bf16* __restrict__ A1hi, const bf16* __restrict__ A1lo,
           const bf16* __restrict__ A2hi, const bf16* __restrict__ A2lo,
           const bf16* __restrict__ Wh,   const bf16* __restrict__ Wl,
           const float* __restrict__ bias0, const float* __restrict__ bias1,
           const float* __restrict__ bias2,
           float* __restrict__ C,
           bf16* __restrict__ C0hi, bf16* __restrict__ C0lo,
           bf16* __restrict__ C1hi, bf16* __restrict__ C1lo,
           bf16* __restrict__ C2hi, bf16* __restrict__ C2lo)
{
    extern __shared__ char smc[];
    const uint32_t sbase = smem_u32(smc);
    const int z = blockIdx.z;
    const bf16* Ahi = (z == 0) ? A0hi : (z == 1) ? A1hi : A2hi;
    const bf16* Alo = (z == 0) ? A0lo : (z == 1) ? A1lo : A2lo;
    const bf16* Bhi = Wh + (size_t)z * DM * DM;
    const bf16* Blo = Wl + (size_t)z * DM * DM;
    const float* bias = (z == 0) ? bias0 : (z == 1) ? bias1 : bias2;
    bf16* Chi = (z == 0) ? C0hi : (z == 1) ? C1hi : C2hi;
    bf16* Clo = (z == 0) ? C0lo : (z == 1) ? C1lo : C2lo;

    const int tid  = threadIdx.x;
    const int wid  = tid >> 5;
    const int lane = tid & 31;
    const int M0 = (wid & 3) * 32;
    const int N0 = (wid >> 2) * 64;
    const int aRow0 = blockIdx.y * 128;
    const int bRow0 = blockIdx.x * 128;

    const int la_row = (lane & 7) + ((lane >> 3) & 1) * 8;
    const int la_k   = (lane >> 4) * 8;
    const uint32_t aoff = (uint32_t)((M0 + la_row) * ROW_B + la_k * 2);
    const int lb_row = ((lane >> 4) * 8) + (lane & 7);
    const int lb_k   = ((lane >> 3) & 1) * 8;
    const uint32_t boff = (uint32_t)((N0 + lb_row) * ROW_B + lb_k * 2);

    float acc[2][8][4];
    #pragma unroll
    for (int i = 0; i < 2; i++)
        #pragma unroll
        for (int j = 0; j < 8; j++)
            #pragma unroll
            for (int v = 0; v < 4; v++) acc[i][j][v] = 0.f;

    // prologue: fill 3 of 4 ring slots
    load_stage(sbase + 0 * STAGE_B, Ahi, Alo, Bhi, Blo, aRow0, bRow0, 0 * KSTEP, tid);
    asm volatile("cp.async.commit_group;" ::: "memory");
    load_stage(sbase + 1 * STAGE_B, Ahi, Alo, Bhi, Blo, aRow0, bRow0, 1 * KSTEP, tid);
    asm volatile("cp.async.commit_group;" ::: "memory");
    load_stage(sbase + 2 * STAGE_B, Ahi, Alo, Bhi, Blo, aRow0, bRow0, 2 * KSTEP, tid);
    asm volatile("cp.async.commit_group;" ::: "memory");

    for (int kt = 0; kt < NKI; kt++) {
        const uint32_t stg = sbase + (uint32_t)(kt & 3) * STAGE_B;

        if (kt < NKI - 2)       asm volatile("cp.async.wait_group 2;" ::: "memory");
        else if (kt == NKI - 2) asm volatile("cp.async.wait_group 1;" ::: "memory");
        else                    asm volatile("cp.async.wait_group 0;" ::: "memory");
        __syncthreads();   // single barrier; prefetch below targets slot freed last iter

        uint32_t ah[2][4], al[2][4];
        LDSM4(ah[0], stg + 0 * REGION_B + aoff);
        LDSM4(ah[1], stg + 0 * REGION_B + aoff + 16 * ROW_B);
        LDSM4(al[0], stg + 1 * REGION_B + aoff);
        LDSM4(al[1], stg + 1 * REGION_B + aoff + 16 * ROW_B);

        #pragma unroll
        for (int np = 0; np < 4; np++) {
            uint32_t bh[4], bl[4];
            LDSM4(bh, stg + 2 * REGION_B + boff + np * 16 * ROW_B);
            LDSM4(bl, stg + 3 * REGION_B + boff + np * 16 * ROW_B);
            #pragma unroll
            for (int mf = 0; mf < 2; mf++) {
                float* d0 = acc[mf][np * 2 + 0];
                float* d1 = acc[mf][np * 2 + 1];
                MMA16816(d0, ah[mf], bh[0], bh[1]);
                MMA16816(d1, ah[mf], bh[2], bh[3]);
                MMA16816(d0, ah[mf], bl[0], bl[1]);
                MMA16816(d1, ah[mf], bl[2], bl[3]);
                MMA16816(d0, al[mf], bh[0], bh[1]);
                MMA16816(d1, al[mf], bh[2], bh[3]);
            }
        }

        if (kt + 3 < NKI) {
            load_stage(sbase + (uint32_t)((kt + 3) & 3) * STAGE_B, Ahi, Alo, Bhi, Blo,
                       aRow0, bRow0, (kt + 3) * KSTEP, tid);
            asm volatile("cp.async.commit_group;" ::: "memory");
        }
    }

    #pragma unroll
    for (int mf = 0; mf < 2; mf++) {
        const int row = aRow0 + M0 + mf * 16 + (lane >> 2);
        #pragma unroll
        for (int nf = 0; nf < 8; nf++) {
            const int col = bRow0 + N0 + nf * 8 + (lane & 3) * 2;
            const float b0 = bias[col], b1 = bias[col + 1];
            float f0 = acc[mf][nf][0] + b0, f1 = acc[mf][nf][1] + b1;
            float f2 = acc[mf][nf][2] + b0, f3 = acc[mf][nf][3] + b1;
            if (MODE == 0) {
                *(float2*)(C + (size_t)row * DM + col)       = make_float2(f0, f1);
                *(float2*)(C + (size_t)(row + 8) * DM + col) = make_float2(f2, f3);
            } else {
                uint32_t uh0 = packbf(f0, f1);
                float e0 = __uint_as_float(uh0 << 16);
                float e1 = __uint_as_float(uh0 & 0xffff0000u);
                uint32_t ul0 = packbf(f0 - e0, f1 - e1);
                uint32_t uh1 = packbf(f2, f3);
                float e2 = __uint_as_float(uh1 << 16);
                float e3 = __uint_as_float(uh1 & 0xffff0000u);
                uint32_t ul1 = packbf(f2 - e2, f3 - e3);
                *(uint32_t*)(Chi + (size_t)row * DM + col)       = uh0;
                *(uint32_t*)(Clo + (size_t)row * DM + col)       = ul0;
                *(uint32_t*)(Chi + (size_t)(row + 8) * DM + col) = uh1;
                *(uint32_t*)(Clo + (size_t)(row + 8) * DM + col) = ul1;
            }
        }
    }
}

// ------------------------- hi/lo split (3 inputs batched) -------------------
__global__ __launch_bounds__(256)
void split_act3(const float4* __restrict__ in0, const float4* __restrict__ in1,
                const float4* __restrict__ in2, bf16* __restrict__ hi,
                bf16* __restrict__ lo, int n4)
{
    int i = blockIdx.x * 256 + threadIdx.x;
    if (i >= n4) return;
    const int y = blockIdx.y;
    const float4* in = (y == 0) ? in0 : (y == 1) ? in1 : in2;
    const size_t o = (size_t)y * (size_t)n4 * 4 + (size_t)i * 4;
    float4 v = in[i];
    uint32_t h0 = packbf(v.x, v.y);
    uint32_t h1 = packbf(v.z, v.w);
    float e0 = __uint_as_float(h0 << 16), e1 = __uint_as_float(h0 & 0xffff0000u);
    float e2 = __uint_as_float(h1 << 16), e3 = __uint_as_float(h1 & 0xffff0000u);
    uint32_t l0 = packbf(v.x - e0, v.y - e1);
    uint32_t l1 = packbf(v.z - e2, v.w - e3);
    *(uint2*)(hi + o) = make_uint2(h0, h1);
    *(uint2*)(lo + o) = make_uint2(l0, l1);
}

// ------------------------- weight transpose + split (4 batched) -------------
__global__ __launch_bounds__(256)
void transpose_split_w4(const float* __restrict__ W0, const float* __restrict__ W1,
                        const float* __restrict__ W2, const float* __restrict__ W3,
                        bf16* __restrict__ hi, bf16* __restrict__ lo)
{
    __shared__ float t[32][33];
    const int z = blockIdx.z;
    const float* W = (z == 0) ? W0 : (z == 1) ? W1 : (z == 2) ? W2 : W3;
    const size_t zofs = (size_t)z * DM * DM;
    const int n0 = blockIdx.x * 32;
    const int k0 = blockIdx.y * 32;
    const int tx = threadIdx.x & 31;
    const int ty = threadIdx.x >> 5;
    #pragma unroll
    for (int r = ty; r < 32; r += 8)
        t[r][tx] = W[(size_t)(k0 + r) * DM + n0 + tx];
    __syncthreads();
    #pragma unroll
    for (int r = ty; r < 32; r += 8) {
        float x = t[tx][r];
        bf16 h = __float2bfloat16_rn(x);
        size_t o = zofs + (size_t)(n0 + r) * DM + k0 + tx;
        hi[o] = h;
        lo[o] = __float2bfloat16_rn(x - __bfloat162float(h));
    }
}

// ------------------------- flash attention (tensor-core bf16x3) -------------
// Br=64 q rows per CTA (4 warps x 16 rows), Bc=64, 2-stage KV ring. (R5-proven)
#define FROW   144
#define FREG   (64 * FROW)            // 9216
#define FSTAGE (4 * FREG + 256)       // 37120
#define FLASH_SMEM (2 * FSTAGE)       // 74240

__device__ __forceinline__ void load_kv_stage(
    uint32_t stg,
    const bf16* __restrict__ Khi, const bf16* __restrict__ Klo,
    const bf16* __restrict__ Vhi, const bf16* __restrict__ Vlo,
    const int* __restrict__ mask, int b, int hcol, int k0, int tid)
{
    #pragma unroll
    for (int i = 0; i < 4; i++) {
        const int c = tid + 128 * i;
        const int r = c >> 3;
        const int cc = c & 7;
        const uint32_t so = (uint32_t)(r * FROW + cc * 16);
        const size_t g = (size_t)(b * S_LEN + k0 + r) * DM + hcol + cc * 8;
        cpa16(stg + 0 * FREG + so, Khi + g);
        cpa16(stg + 1 * FREG + so, Klo + g);
        cpa16(stg + 2 * FREG + so, Vhi + g);
        cpa16(stg + 3 * FREG + so, Vlo + g);
    }
    if (tid < 16)
        cpa16(stg + 4 * FREG + tid * 16, mask + b * S_LEN + k0 + tid * 4);
}

__global__ __launch_bounds__(128)
void flash_attn_tc(const bf16* __restrict__ Qhi, const bf16* __restrict__ Qlo,
                   const bf16* __restrict__ Khi, const bf16* __restrict__ Klo,
                   const bf16* __restrict__ Vhi, const bf16* __restrict__ Vlo,
                   const int* __restrict__ mask,
                   bf16* __restrict__ Ohi, bf16* __restrict__ Olo)
{
    extern __shared__ char smf[];
    const uint32_t base = smem_u32(smf);
    const int tid  = threadIdx.x;
    const int wid  = tid >> 5;
    const int lane = tid & 31;
    const int b  = blockIdx.z;
    const int h  = blockIdx.y;
    const int q0 = blockIdx.x * 64;
    const int hcol = h * DK;

    #pragma unroll
    for (int i = 0; i < 4; i++) {
        const int c = tid + 128 * i;
        const int r = c >> 3;
        const int cc = c & 7;
        const uint32_t so = (uint32_t)(r * FROW + cc * 16);
        const size_t g = (size_t)(b * S_LEN + q0 + r) * DM + hcol + cc * 8;
        cpa16(base + so,        Qhi + g);
        cpa16(base + FREG + so, Qlo + g);
    }
    asm volatile("cp.async.commit_group;" ::: "memory");
    asm volatile("cp.async.wait_group 0;" ::: "memory");
    __syncthreads();

    const int la_row = (lane & 7) + ((lane >> 3) & 1) * 8;
    const int la_k   = (lane >> 4) * 8;
    uint32_t qh[4][4], ql[4][4];
    {
        const uint32_t qaddr = base + (uint32_t)((wid * 16 + la_row) * FROW + la_k * 2);
        #pragma unroll
        for (int kf = 0; kf < 4; kf++) {
            LDSM4(qh[kf], qaddr + kf * 32);
            LDSM4(ql[kf], qaddr + FREG + kf * 32);
        }
    }
    __syncthreads();

    load_kv_stage(base,          Khi, Klo, Vhi, Vlo, mask, b, hcol, 0,  tid);
    asm volatile("cp.async.commit_group;" ::: "memory");
    load_kv_stage(base + FSTAGE, Khi, Klo, Vhi, Vlo, mask, b, hcol, 64, tid);
    asm volatile("cp.async.commit_group;" ::: "memory");

    const int lb_row = ((lane >> 4) * 8) + (lane & 7);
    const int lb_k   = ((lane >> 3) & 1) * 8;
    const int vb_row = (lane & 7) + ((lane >> 3) & 1) * 8;
    const int vb_col = (lane >> 4) * 8;

    float m2[2] = {-INFINITY, -INFINITY};
    float l2[2] = {0.f, 0.f};
    float oacc[4][8];
    #pragma unroll
    for (int i = 0; i < 4; i++)
        #pragma unroll
        for (int j = 0; j < 8; j++) oacc[i][j] = 0.f;

    const float C1   = 0.04508422f;          // log2(e)/32
    const float MNEG = -1e20f * 0.04508422f;

    for (int t = 0; t < S_LEN / 64; t++) {
        const uint32_t stg = base + (uint32_t)(t & 1) * FSTAGE;

        if (t == S_LEN / 64 - 1) asm volatile("cp.async.wait_group 0;" ::: "memory");
        else                     asm volatile("cp.async.wait_group 1;" ::: "memory");
        __syncthreads();

        float sacc[4][8];
        #pragma unroll
        for (int np = 0; np < 4; np++)
            #pragma unroll
            for (int j = 0; j < 8; j++) sacc[np][j] = 0.f;

        #pragma unroll
        for (int np = 0; np < 4; np++) {
            const uint32_t kb = stg + (uint32_t)((np * 16 + lb_row) * FROW + lb_k * 2);
            float* d0 = &sacc[np][0];
            float* d1 = &sacc[np][4];
            #pragma unroll
            for (int kf = 0; kf < 4; kf++) {
                uint32_t kh[4], kl[4];
                LDSM4(kh, kb + kf * 32);
                LDSM4(kl, kb + FREG + kf * 32);
                MMA16816(d0, qh[kf], kh[0], kh[1]);
                MMA16816(d1, qh[kf], kh[2], kh[3]);
                MMA16816(d0, qh[kf], kl[0], kl[1]);
                MMA16816(d1, qh[kf], kl[2], kl[3]);
                MMA16816(d0, ql[kf], kh[0], kh[1]);
                MMA16816(d1, ql[kf], kh[2], kh[3]);
            }
        }

        const char* mbase = smf + (t & 1) * FSTAGE + 4 * FREG;
        #pragma unroll
        for (int np = 0; np < 4; np++) {
            #pragma unroll
            for (int h2 = 0; h2 < 2; h2++) {
                const int col = np * 16 + h2 * 8 + 2 * (lane & 3);
                int2 mv = *(const int2*)(mbase + col * 4);
                float* d = &sacc[np][h2 * 4];
                d[0] = mv.x ? d[0] * C1 : MNEG;
                d[1] = mv.y ? d[1] * C1 : MNEG;
                d[2] = mv.x ? d[2] * C1 : MNEG;
                d[3] = mv.y ? d[3] * C1 : MNEG;
            }
        }

        float mx0 = -INFINITY, mx1 = -INFINITY;
        #pragma unroll
        for (int np = 0; np < 4; np++)
            #pragma unroll
            for (int h2 = 0; h2 < 2; h2++) {
                float* d = &sacc[np][h2 * 4];
                mx0 = fmaxf(mx0, fmaxf(d[0], d[1]));
                mx1 = fmaxf(mx1, fmaxf(d[2], d[3]));
            }
        mx0 = fmaxf(mx0, __shfl_xor_sync(0xffffffffu, mx0, 1));
        mx0 = fmaxf(mx0, __shfl_xor_sync(0xffffffffu, mx0, 2));
        mx1 = fmaxf(mx1, __shfl_xor_sync(0xffffffffu, mx1, 1));
        mx1 = fmaxf(mx1, __shfl_xor_sync(0xffffffffu, mx1, 2));

        const float mn0 = fmaxf(m2[0], mx0);
        const float mn1 = fmaxf(m2[1], mx1);
        const float a0 = ex2(m2[0] - mn0);
        const float a1 = ex2(m2[1] - mn1);
        m2[0] = mn0; m2[1] = mn1;

        float ls0 = 0.f, ls1 = 0.f;
        #pragma unroll
        for (int np = 0; np < 4; np++)
            #pragma unroll
            for (int h2 = 0; h2 < 2; h2++) {
                float* d = &sacc[np][h2 * 4];
                d[0] = ex2(d[0] - mn0);
                d[1] = ex2(d[1] - mn0);
                d[2] = ex2(d[2] - mn1);
                d[3] = ex2(d[3] - mn1);
                ls0 += d[0] + d[1];
                ls1 += d[2] + d[3];
            }
        ls0 += __shfl_xor_sync(0xffffffffu, ls0, 1);
        ls0 += __shfl_xor_sync(0xffffffffu, ls0, 2);
        ls1 += __shfl_xor_sync(0xffffffffu, ls1, 1);
        ls1 += __shfl_xor_sync(0xffffffffu, ls1, 2);
        l2[0] = l2[0] * a0 + ls0;
        l2[1] = l2[1] * a1 + ls1;

        #pragma unroll
        for (int np = 0; np < 4; np++)
            #pragma unroll
            for (int h2 = 0; h2 < 2; h2++) {
                float* d = &oacc[np][h2 * 4];
                d[0] *= a0; d[1] *= a0; d[2] *= a1; d[3] *= a1;
            }

        uint32_t phi[4][4], plo[4][4];
        #pragma unroll
        for (int np = 0; np < 4; np++) {
            #pragma unroll
            for (int h2 = 0; h2 < 2; h2++) {
                float* d = &sacc[np][h2 * 4];
                uint32_t u01 = packbf(d[0], d[1]);
                uint32_t u23 = packbf(d[2], d[3]);
                float e0 = __uint_as_float(u01 << 16), e1 = __uint_as_float(u01 & 0xffff0000u);
                float e2 = __uint_as_float(u23 << 16), e3 = __uint_as_float(u23 & 0xffff0000u);
                phi[np][h2 * 2 + 0] = u01;
                phi[np][h2 * 2 + 1] = u23;
                plo[np][h2 * 2 + 0] = packbf(d[0] - e0, d[1] - e1);
                plo[np][h2 * 2 + 1] = packbf(d[2] - e2, d[3] - e3);
            }
        }

        #pragma unroll
        for (int npd = 0; npd < 4; npd++) {
            float* o0 = &oacc[npd][0];
            float* o1 = &oacc[npd][4];
            #pragma unroll
            for (int kf = 0; kf < 4; kf++) {
                const uint32_t va = stg + 2 * FREG +
                    (uint32_t)((kf * 16 + vb_row) * FROW + (npd * 16 + vb_col) * 2);
                uint32_t vh[4], vl[4];
                LDSM4T(vh, va);
                LDSM4T(vl, va + FREG);
                MMA16816(o0, phi[kf], vh[0], vh[1]);
                MMA16816(o1, phi[kf], vh[2], vh[3]);
                MMA16816(o0, phi[kf], vl[0], vl[1]);
                MMA16816(o1, phi[kf], vl[2], vl[3]);
                MMA16816(o0, plo[kf], vh[0], vh[1]);
                MMA16816(o1, plo[kf], vh[2], vh[3]);
            }
        }

        __syncthreads();
        if (t + 2 < S_LEN / 64) {
            load_kv_stage(stg, Khi, Klo, Vhi, Vlo, mask, b, hcol, (t + 2) * 64, tid);
            asm volatile("cp.async.commit_group;" ::: "memory");
        }
    }

    const float inv0 = 1.f / l2[0];
    const float inv1 = 1.f / l2[1];
    const int r0 = q0 + wid * 16 + (lane >> 2);
    const size_t row0 = (size_t)(b * S_LEN + r0) * DM + hcol;
    const size_t row1 = row0 + 8 * DM;
    #pragma unroll
    for (int npd = 0; npd < 4; npd++) {
        #pragma unroll
        for (int h2 = 0; h2 < 2; h2++) {
            const int c = npd * 16 + h2 * 8 + 2 * (lane & 3);
            float* d = &oacc[npd][h2 * 4];
            float f0 = d[0] * inv0, f1 = d[1] * inv0;
            float f2 = d[2] * inv1, f3 = d[3] * inv1;
            uint32_t uh0 = packbf(f0, f1);
            float e0 = __uint_as_float(uh0 << 16), e1 = __uint_as_float(uh0 & 0xffff0000u);
            uint32_t ul0 = packbf(f0 - e0, f1 - e1);
            uint32_t uh1 = packbf(f2, f3);
            float e2 = __uint_as_float(uh1 << 16), e3 = __uint_as_float(uh1 & 0xffff0000u);
            uint32_t ul1 = packbf(f2 - e2, f3 - e3);
            *(uint32_t*)(Ohi + row0 + c) = uh0;
            *(uint32_t*)(Olo + row0 + c) = ul0;
            *(uint32_t*)(Ohi + row1 + c) = uh1;
            *(uint32_t*)(Olo + row1 + c) = ul1;
        }
    }
}

// ---------------------------------------------------------------------------
extern "C" void kernel_launch(void* const* d_in, const int* in_sizes, int n_in,
                              void* d_out, int out_size)
{
    const float* values = (const float*)d_in[0];
    const float* keys   = (const float*)d_in[1];
    const float* query  = (const float*)d_in[2];
    const int*   mask   = (const int*)  d_in[3];
    const float* Wq = (const float*)d_in[4];
    const float* bq = (const float*)d_in[5];
    const float* Wk = (const float*)d_in[6];
    const float* bk = (const float*)d_in[7];
    const float* Wv = (const float*)d_in[8];
    const float* bv = (const float*)d_in[9];
    const float* Wo = (const float*)d_in[10];
    const float* bo = (const float*)d_in[11];
    float* out = (float*)d_out;

    bf16 *Qhi, *Qlo, *Khi, *Klo, *Vhi, *Vlo, *Ohi, *Olo, *A3hi, *A3lo, *Whi, *Wlo;
    cudaGetSymbolAddress((void**)&Qhi, g_Qhi);
    cudaGetSymbolAddress((void**)&Qlo, g_Qlo);
    cudaGetSymbolAddress((void**)&Khi, g_Khi);
    cudaGetSymbolAddress((void**)&Klo, g_Klo);
    cudaGetSymbolAddress((void**)&Vhi, g_Vhi);
    cudaGetSymbolAddress((void**)&Vlo, g_Vlo);
    cudaGetSymbolAddress((void**)&Ohi, g_Ohi);
    cudaGetSymbolAddress((void**)&Olo, g_Olo);
    cudaGetSymbolAddress((void**)&A3hi, g_A3hi);
    cudaGetSymbolAddress((void**)&A3lo, g_A3lo);
    cudaGetSymbolAddress((void**)&Whi, g_Whi);
    cudaGetSymbolAddress((void**)&Wlo, g_Wlo);

    cudaFuncSetAttribute(gemm3<0>, cudaFuncAttributeMaxDynamicSharedMemorySize, GEMM_SMEM);
    cudaFuncSetAttribute(gemm3<1>, cudaFuncAttributeMaxDynamicSharedMemorySize, GEMM_SMEM);
    cudaFuncSetAttribute(flash_attn_tc, cudaFuncAttributeMaxDynamicSharedMemorySize, FLASH_SMEM);

    const size_t SZ = (size_t)M_ROWS * DM;
    const int n4 = (int)(SZ / 4);

    transpose_split_w4<<<dim3(DM / 32, DM / 32, 4), 256>>>(Wq, Wk, Wv, Wo, Whi, Wlo);

    split_act3<<<dim3(n4 / 256, 3), 256>>>((const float4*)query, (const float4*)keys,
                                           (const float4*)values, A3hi, A3lo, n4);

    gemm3<1><<<dim3(DM / 128, M_ROWS / 128, 3), 256, GEMM_SMEM>>>(
        A3hi, A3lo, A3hi + SZ, A3lo + SZ, A3hi + 2 * SZ, A3lo + 2 * SZ,
        Whi, Wlo, bq, bk, bv,
        nullptr, Qhi, Qlo, Khi, Klo, Vhi, Vlo);

    dim3 gattn(S_LEN / 64, HEADS, BATCH);   // (16, 16, 8)
    flash_attn_tc<<<gattn, 128, FLASH_SMEM>>>(Qhi, Qlo, Khi, Klo, Vhi, Vlo, mask, Ohi, Olo);

    gemm3<0><<<dim3(DM / 128, M_ROWS / 128, 1), 256, GEMM_SMEM>>>(
        Ohi, Olo, nullptr, nullptr, nullptr, nullptr,
        Whi + 3 * (size_t)DM * DM, Wlo + 3 * (size_t)DM * DM, bo, nullptr, nullptr,
        out, nullptr, nullptr, nullptr, nullptr, nullptr, nullptr);
}